// round 11
// baseline (speedup 1.0000x reference)
#include <cuda_runtime.h>
#include <math.h>

// Problem constants (fixed shapes)
#define B_   4
#define C_   64
#define H_   282
#define W_   282
#define P_   12000
#define HW_  (H_ * W_)        // 79524
#define NQ_  (HW_ / 4)        // 19881 float4-quads per channel image

#define IDX_BLOCKS_ ((B_ * P_ + 255) / 256)   // 188

// Scratch (device global; zero-initialized at module load, then self-reset by
// k_gather every call -> no reset kernel, no extra dirty scratch traffic).
__device__ __align__(16) int g_winner[B_ * HW_];   // (p+1) of winner, 0 = empty

// ---------------------------------------------------------------------------
// Kernel 1: per (b, p) compute target cell; atomicMax(p+1) == sequential
// last-update-wins of XLA scatter (highest p wins). Index math matches XLA
// fast-math lowering: (x + 22) * 6.25f (bit-verified in R2). Invalid pillars
// (x == 0) map OOB in the reference and are dropped.
// ---------------------------------------------------------------------------
__global__ void k_index(const float* __restrict__ pin) {
    int i = blockIdx.x * blockDim.x + threadIdx.x;   // i = b*P + p
    if (i >= B_ * P_) return;
    int b = i / P_;
    int p = i - b * P_;

    float x = pin[(b * 2 + 0) * P_ + p];
    if (x == 0.0f) return;
    float y = pin[(b * 2 + 1) * P_ + p];

    int xg = (int)floorf(__fmul_rn(__fadd_rn(x, 22.0f), 6.25f));
    int yg = (int)floorf(__fmul_rn(__fadd_rn(y, 22.0f), 6.25f));
    xg = min(max(xg, 0), W_ - 1);
    yg = min(max(yg, 0), H_ - 1);
    atomicMax(&g_winner[b * HW_ + yg * W_ + xg], p + 1);
}

// ---------------------------------------------------------------------------
// Kernel 2: GATHER (R4 structure — fastest measured — minus the transpose).
// One thread per (b, x-quad) owns ALL 64 channels:
//  - one int4 winner read (coalesced), immediate self-reset (unique owner),
//  - per channel: up to 4 scattered scalar feat reads (L2-resident 12 MB
//    footprint; R3 proved this is as fast as transposed reads) and one
//    coalesced float4 store.
// Stores use __stcs (evict-first streaming): canvas lines drain to DRAM
// eagerly instead of piling 81 MB of dirty L2 that stalls the next replay
// iteration's first stores (the R10 k_reset 4.2us smoking gun).
// No g_tf: saves ~24 MB/iter of DRAM write+read traffic vs R4.
// ---------------------------------------------------------------------------
__global__ void __launch_bounds__(256) k_gather(const float* __restrict__ feats,
                                                float4* __restrict__ out) {
    int t = blockIdx.x * blockDim.x + threadIdx.x;
    if (t >= B_ * NQ_) return;
    int b  = t / NQ_;
    int q4 = t - b * NQ_;

    int4* w4 = (int4*)g_winner;
    int4 w = w4[t];
    w4[t] = make_int4(0, 0, 0, 0);        // self-reset for next call

    int ix = w.x - 1, iy = w.y - 1, iz = w.z - 1, iw = w.w - 1;
    const float* fb = feats + (size_t)b * C_ * P_;
    float4* ob = out + (size_t)b * C_ * NQ_ + q4;

    #pragma unroll 8
    for (int c = 0; c < C_; c++) {
        const float* f = fb + (size_t)c * P_;
        float4 v;
        v.x = (ix >= 0) ? __ldg(f + ix) : 0.0f;
        v.y = (iy >= 0) ? __ldg(f + iy) : 0.0f;
        v.z = (iz >= 0) ? __ldg(f + iz) : 0.0f;
        v.w = (iw >= 0) ? __ldg(f + iw) : 0.0f;
        __stcs(ob + (size_t)c * NQ_, v);
    }
}

// ---------------------------------------------------------------------------
extern "C" void kernel_launch(void* const* d_in, const int* in_sizes, int n_in,
                              void* d_out, int out_size) {
    const float* pfn_input  = (const float*)d_in[0];   // (4, 2, 12000, 1)
    const float* pfn_output = (const float*)d_in[1];   // (4, 64, 12000)
    float* out = (float*)d_out;                        // (4, 64, 282, 282)

    k_index <<<IDX_BLOCKS_,               256>>>(pfn_input);
    k_gather<<<(B_ * NQ_ + 255) / 256,    256>>>(pfn_output, (float4*)out);
}

// round 12
// speedup vs baseline: 1.0424x; 1.0424x over previous
#include <cuda_runtime.h>
#include <math.h>

// Problem constants (fixed shapes)
#define B_   4
#define C_   64
#define H_   282
#define W_   282
#define P_   12000
#define HW_  (H_ * W_)        // 79524
#define NQ_  (HW_ / 4)        // 19881 float4-quads per channel image
#define NT_  (B_ * NQ_ * 4)   // 318096 gather threads (4 cg per quad)

#define IDX_BLOCKS_ ((B_ * P_ + 255) / 256)   // 188

// Scratch (device global; zero-initialized at module load, then self-reset by
// k_gather every call -> no reset kernel, no transpose scratch: per-iteration
// DRAM traffic is canvas 81MB + feats 12MB + ~4MB, the measured binder).
__device__ __align__(16) int g_winner[B_ * HW_];   // (p+1) of winner, 0 = empty

// ---------------------------------------------------------------------------
// Kernel 1: per (b, p) compute target cell; atomicMax(p+1) == sequential
// last-update-wins of XLA scatter (highest p wins). Index math matches XLA
// fast-math lowering: (x + 22) * 6.25f (bit-verified in R2). Invalid pillars
// (x == 0) map OOB in the reference and are dropped.
// ---------------------------------------------------------------------------
__global__ void k_index(const float* __restrict__ pin) {
    int i = blockIdx.x * blockDim.x + threadIdx.x;   // i = b*P + p
    if (i >= B_ * P_) return;
    int b = i / P_;
    int p = i - b * P_;

    float x = pin[(b * 2 + 0) * P_ + p];
    if (x == 0.0f) return;
    float y = pin[(b * 2 + 1) * P_ + p];

    int xg = (int)floorf(__fmul_rn(__fadd_rn(x, 22.0f), 6.25f));
    int yg = (int)floorf(__fmul_rn(__fadd_rn(y, 22.0f), 6.25f));
    xg = min(max(xg, 0), W_ - 1);
    yg = min(max(yg, 0), H_ - 1);
    atomicMax(&g_winner[b * HW_ + yg * W_ + xg], p + 1);
}

// ---------------------------------------------------------------------------
// Kernel 2: GATHER — R3's proven shape (16 channels/thread, 1243 blocks,
// ~24.5us measured) with cg interleaved into the lane index:
//   t = (b*NQ + q4)*4 + cg  ->  warp = 8 consecutive quads x 4 cg groups.
//  - winner read: 32 lanes cover 8 consecutive int4s (one 128B coalesced
//    wavefront; 4 lanes share each via L1),
//  - __syncwarp() then cg==0 lanes self-reset (all warp lanes reached the
//    sync -> full-mask legal; read-before-reset ordered within the warp),
//  - 16 iterations: 4 predicated scalar feat reads (L2-resident 12MB) + one
//    float4 store. Warp stores cover 4 full 128B lines per instr (coalesced).
// NORMAL stores (no __stcs): L2 assembles full lines before writeback,
// avoiding R11's partial-line write amplification.
// ---------------------------------------------------------------------------
__global__ void __launch_bounds__(256) k_gather(const float* __restrict__ feats,
                                                float4* __restrict__ out) {
    int t = blockIdx.x * blockDim.x + threadIdx.x;
    bool valid = (t < NT_);
    int tc = valid ? t : 0;               // keep whole warp alive through sync
    int cg = tc & 3;                      // channel group of 16
    int tq = tc >> 2;                     // b*NQ + q4
    int b  = tq / NQ_;
    int q4 = tq - b * NQ_;

    int4* w4 = (int4*)g_winner;
    int4 w = make_int4(0, 0, 0, 0);
    if (valid) w = w4[tq];
    __syncwarp();                         // all lanes present: reads done
    if (valid && cg == 0) w4[tq] = make_int4(0, 0, 0, 0);   // self-reset
    if (!valid) return;

    int ix = w.x - 1, iy = w.y - 1, iz = w.z - 1, iw = w.w - 1;
    const float* fb = feats + ((size_t)b * C_ + cg * 16) * P_;
    float4*      ob = out   + ((size_t)b * C_ + cg * 16) * NQ_ + q4;

    #pragma unroll
    for (int c = 0; c < 16; c++) {
        const float* f = fb + (size_t)c * P_;
        float4 v;
        v.x = (ix >= 0) ? __ldg(f + ix) : 0.0f;
        v.y = (iy >= 0) ? __ldg(f + iy) : 0.0f;
        v.z = (iz >= 0) ? __ldg(f + iz) : 0.0f;
        v.w = (iw >= 0) ? __ldg(f + iw) : 0.0f;
        ob[(size_t)c * NQ_] = v;
    }
}

// ---------------------------------------------------------------------------
extern "C" void kernel_launch(void* const* d_in, const int* in_sizes, int n_in,
                              void* d_out, int out_size) {
    const float* pfn_input  = (const float*)d_in[0];   // (4, 2, 12000, 1)
    const float* pfn_output = (const float*)d_in[1];   // (4, 64, 12000)
    float* out = (float*)d_out;                        // (4, 64, 282, 282)

    k_index <<<IDX_BLOCKS_,            256>>>(pfn_input);
    k_gather<<<(NT_ + 255) / 256,      256>>>(pfn_output, (float4*)out);
}

// round 13
// speedup vs baseline: 1.2336x; 1.1834x over previous
#include <cuda_runtime.h>
#include <math.h>

// Problem constants (fixed shapes)
#define B_   4
#define C_   64
#define H_   282
#define W_   282
#define P_   12000
#define HW_  (H_ * W_)        // 79524
#define NQ_  (HW_ / 4)        // 19881 float4-quads per channel image

#define PT_  (P_ / 32)        // 375 pillar tiles (exact)
#define TRANS_BLOCKS_ (B_ * PT_)                  // 1500 (64ch x 32p tiles)
#define IDX_BLOCKS_   ((B_ * P_ + 255) / 256)     // 188

// Scratch (device globals; zero-initialized at module load; g_winner
// self-resets inside k_gather -> no reset kernel)
__device__ __align__(16) int   g_winner[B_ * HW_];     // (p+1) of winner, 0 = empty
__device__ __align__(16) float g_tf[B_ * P_ * C_];     // feats transposed to (B, P, C)

// ---------------------------------------------------------------------------
// Kernel 1 (fused): blocks [0, 1500) transpose feats (B,C,P) -> g_tf (B,P,C)
// with a float4-vectorized 64ch x 32p tile (2 float4 loads + 2 float4 stores
// per thread; 4x fewer memory instrs than the R4 scalar version); blocks
// [1500, 1688) compute per-pillar cells and atomicMax(p+1) into g_winner
// (sequential last-update-wins == max p). Index math matches XLA fast-math
// lowering: (x + 22) * 6.25f (bit-verified in R2).
// ---------------------------------------------------------------------------
__global__ void k_prep(const float* __restrict__ feats,
                       const float* __restrict__ pin) {
    if (blockIdx.x < TRANS_BLOCKS_) {
        __shared__ float tile[64][33];
        int bid   = blockIdx.x;
        int b     = bid / PT_;
        int ptile = bid - b * PT_;
        int p0    = ptile * 32;
        int tid   = threadIdx.x;

        // load 64x32 tile: 512 float4s along p, 2 per thread (coalesced)
        #pragma unroll
        for (int r = 0; r < 2; r++) {
            int i  = tid + r * 256;           // 0..511
            int c  = i >> 3;                  // 0..63
            int pq = i & 7;                   // 0..7 -> p offset pq*4
            float4 v = *(const float4*)(feats + ((size_t)b * C_ + c) * P_ + p0 + pq * 4);
            tile[c][pq * 4 + 0] = v.x;
            tile[c][pq * 4 + 1] = v.y;
            tile[c][pq * 4 + 2] = v.z;
            tile[c][pq * 4 + 3] = v.w;
        }
        __syncthreads();

        // store transposed: 512 float4s along c, 2 per thread (coalesced)
        #pragma unroll
        for (int r = 0; r < 2; r++) {
            int i  = tid + r * 256;
            int p  = i >> 4;                  // 0..31
            int cq = i & 15;                  // 0..15 -> c offset cq*4
            float4 v = make_float4(tile[cq * 4 + 0][p], tile[cq * 4 + 1][p],
                                   tile[cq * 4 + 2][p], tile[cq * 4 + 3][p]);
            *(float4*)(g_tf + ((size_t)b * P_ + p0 + p) * C_ + cq * 4) = v;
        }
    } else {
        int i = (blockIdx.x - TRANS_BLOCKS_) * 256 + threadIdx.x;  // b*P + p
        if (i >= B_ * P_) return;
        int b = i / P_;
        int p = i - b * P_;

        float x = pin[(b * 2 + 0) * P_ + p];
        if (x == 0.0f) return;            // invalid pillars dropped (OOB in ref)
        float y = pin[(b * 2 + 1) * P_ + p];

        int xg = (int)floorf(__fmul_rn(__fadd_rn(x, 22.0f), 6.25f));
        int yg = (int)floorf(__fmul_rn(__fadd_rn(y, 22.0f), 6.25f));
        xg = min(max(xg, 0), W_ - 1);
        yg = min(max(yg, 0), H_ - 1);
        atomicMax(&g_winner[b * HW_ + yg * W_ + xg], p + 1);  // 0 = empty
    }
}

// ---------------------------------------------------------------------------
// Kernel 2: GATHER — VERBATIM the R4 kernel (fastest measured: 23.2us).
// One thread per (b, x-quad) owns ALL 64 channels: one int4 winner read +
// race-free self-reset, then per 4-channel group one float4 load per filled
// lane from the pillar's contiguous transposed row, 4x4 register transpose,
// 4 coalesced float4 stores. Transposed reads are the proven fast variant
// (23-25us) vs untransposed scalar reads (35-38us, R11/R12).
// ---------------------------------------------------------------------------
__global__ void k_gather(float4* __restrict__ out) {
    int t = blockIdx.x * blockDim.x + threadIdx.x;
    if (t >= B_ * NQ_) return;
    int b  = t / NQ_;
    int q4 = t - b * NQ_;

    int4* w4 = (int4*)g_winner;
    int4 w = w4[t];
    w4[t] = make_int4(0, 0, 0, 0);        // self-reset for next call

    const float* tb = g_tf + (size_t)b * P_ * C_;
    const float4* fx = (w.x > 0) ? (const float4*)(tb + (size_t)(w.x - 1) * C_) : nullptr;
    const float4* fy = (w.y > 0) ? (const float4*)(tb + (size_t)(w.y - 1) * C_) : nullptr;
    const float4* fz = (w.z > 0) ? (const float4*)(tb + (size_t)(w.z - 1) * C_) : nullptr;
    const float4* fw = (w.w > 0) ? (const float4*)(tb + (size_t)(w.w - 1) * C_) : nullptr;

    float4* ob = out + (size_t)b * C_ * NQ_ + q4;
    const float4 Z = make_float4(0.f, 0.f, 0.f, 0.f);

    #pragma unroll 4
    for (int gg = 0; gg < 16; gg++) {     // channel groups of 4
        float4 vx = fx ? __ldg(fx + gg) : Z;
        float4 vy = fy ? __ldg(fy + gg) : Z;
        float4 vz = fz ? __ldg(fz + gg) : Z;
        float4 vw = fw ? __ldg(fw + gg) : Z;

        ob[(size_t)(gg * 4 + 0) * NQ_] = make_float4(vx.x, vy.x, vz.x, vw.x);
        ob[(size_t)(gg * 4 + 1) * NQ_] = make_float4(vx.y, vy.y, vz.y, vw.y);
        ob[(size_t)(gg * 4 + 2) * NQ_] = make_float4(vx.z, vy.z, vz.z, vw.z);
        ob[(size_t)(gg * 4 + 3) * NQ_] = make_float4(vx.w, vy.w, vz.w, vw.w);
    }
}

// ---------------------------------------------------------------------------
extern "C" void kernel_launch(void* const* d_in, const int* in_sizes, int n_in,
                              void* d_out, int out_size) {
    const float* pfn_input  = (const float*)d_in[0];   // (4, 2, 12000, 1)
    const float* pfn_output = (const float*)d_in[1];   // (4, 64, 12000)
    float* out = (float*)d_out;                        // (4, 64, 282, 282)

    k_prep  <<<TRANS_BLOCKS_ + IDX_BLOCKS_, 256>>>(pfn_output, pfn_input);
    k_gather<<<(B_ * NQ_ + 255) / 256,      256>>>((float4*)out);
}